// round 3
// baseline (speedup 1.0000x reference)
#include <cuda_runtime.h>
#include <cuda_bf16.h>
#include <cstdint>

// RAPiD decode:
//   raw:    (nB=64, nA*6=18, nH=128, nW=128) fp32, channel-major
//   out:    (nB, nA*nH*nW, 6) fp32
//
// R2 -> R3: 4 pixels/thread with LDG.128 channel loads. R2 showed a balanced
// profile (DRAM 57 / L1 56 / issue 48) = latency+issue mixed. Halving the
// instruction stream and doubling per-thread MLP pushes the kernel into the
// DRAM-bound regime. Warp stages its 3072B output tile in smem (2-way STS
// conflict, conflict-free drain) and drains with 6 coalesced STG.128 rounds.

namespace {
constexpr int nB = 64;
constexpr int nA = 3;
constexpr int nH = 128;
constexpr int nW = 128;
constexpr int HW = nH * nW;              // 16384 pixels per (b,a) slice
constexpr int WARPS_PER_BLOCK = 8;
constexpr int PIX_PER_THREAD = 4;
constexpr int PIX_PER_WARP = 32 * PIX_PER_THREAD;              // 128
constexpr int PIX_PER_BLOCK = WARPS_PER_BLOCK * PIX_PER_WARP;  // 1024
constexpr int BLOCKS_PER_SLICE = HW / PIX_PER_BLOCK;           // 16
constexpr float ANGLE_RANGE = 360.0f;
}

__device__ __forceinline__ float fsigmoid(float x) {
    return __fdividef(1.0f, 1.0f + __expf(-x));
}

__global__ void __launch_bounds__(256)
rapid_decode_kernel(const float* __restrict__ raw,
                    const float* __restrict__ anchors,
                    const int* __restrict__ img_h_p,
                    const int* __restrict__ img_w_p,
                    float* __restrict__ out)
{
    // 6 floats/pixel * 128 pixels/warp = 768 floats = 3072 B per warp
    __shared__ float stage[WARPS_PER_BLOCK * PIX_PER_WARP * 6];  // 24 KB

    const int tid  = threadIdx.x;
    const int lane = tid & 31;
    const int warp = tid >> 5;

    // block-uniform slice / anchor math (no block straddles a slice)
    const int slice  = blockIdx.x >> 4;                      // / BLOCKS_PER_SLICE
    const int blk_in = blockIdx.x & (BLOCKS_PER_SLICE - 1);
    const int b = slice / nA;
    const int a = slice - b * nA;

    const int warp_hw = blk_in * PIX_PER_BLOCK + warp * PIX_PER_WARP;
    const int hw0 = warp_hw + PIX_PER_THREAD * lane;         // 4-aligned
    const int h   = hw0 >> 7;                                // all 4 px same row
    const int w0  = hw0 & (nW - 1);

    const float img_h = img_h_p ? (float)__ldg(img_h_p) : 1024.0f;
    const float img_w = img_w_p ? (float)__ldg(img_w_p) : 1024.0f;
    const float sx = img_w * (1.0f / (float)nW);
    const float sy = img_h * (1.0f / (float)nH);

    const float aw = __ldg(&anchors[a * 2 + 0]);
    const float ah = __ldg(&anchors[a * 2 + 1]);

    // channel base: raw[(b*18 + a*6 + c)*HW + hw0] -- coalesced LDG.128/channel
    const float* base = raw + ((size_t)(b * (nA * 6) + a * 6) * HW + hw0);
    const float4 rx = *(const float4*)(base + 0 * HW);
    const float4 ry = *(const float4*)(base + 1 * HW);
    const float4 rw = *(const float4*)(base + 2 * HW);
    const float4 rh = *(const float4*)(base + 3 * HW);
    const float4 ra = *(const float4*)(base + 4 * HW);
    const float4 rc = *(const float4*)(base + 5 * HW);

    const float py = (fsigmoid(ry.x + 0.0f), 0.0f);  // placeholder removed below
    (void)py;

    float4* ws = (float4*)(stage + warp * (PIX_PER_WARP * 6)) + 6 * lane;

    {   // pixel 0
        const float px = (fsigmoid(rx.x) + (float)(w0 + 0)) * sx;
        const float pyv = (fsigmoid(ry.x) + (float)h) * sy;
        const float pw = __expf(rw.x) * aw;
        const float ph = __expf(rh.x) * ah;
        const float pa = fsigmoid(ra.x) * ANGLE_RANGE - ANGLE_RANGE * 0.5f;
        const float pc = fsigmoid(rc.x);
        ws[0] = make_float4(px, pyv, pw, ph);
        // pa, pc packed with pixel1 below
        // pixel 1
        const float px1 = (fsigmoid(rx.y) + (float)(w0 + 1)) * sx;
        const float py1 = (fsigmoid(ry.y) + (float)h) * sy;
        ws[1] = make_float4(pa, pc, px1, py1);
        const float pw1 = __expf(rw.y) * aw;
        const float ph1 = __expf(rh.y) * ah;
        const float pa1 = fsigmoid(ra.y) * ANGLE_RANGE - ANGLE_RANGE * 0.5f;
        const float pc1 = fsigmoid(rc.y);
        ws[2] = make_float4(pw1, ph1, pa1, pc1);
        // pixel 2
        const float px2 = (fsigmoid(rx.z) + (float)(w0 + 2)) * sx;
        const float py2 = (fsigmoid(ry.z) + (float)h) * sy;
        const float pw2 = __expf(rw.z) * aw;
        const float ph2 = __expf(rh.z) * ah;
        ws[3] = make_float4(px2, py2, pw2, ph2);
        const float pa2 = fsigmoid(ra.z) * ANGLE_RANGE - ANGLE_RANGE * 0.5f;
        const float pc2 = fsigmoid(rc.z);
        // pixel 3
        const float px3 = (fsigmoid(rx.w) + (float)(w0 + 3)) * sx;
        const float py3 = (fsigmoid(ry.w) + (float)h) * sy;
        ws[4] = make_float4(pa2, pc2, px3, py3);
        const float pw3 = __expf(rw.w) * aw;
        const float ph3 = __expf(rh.w) * ah;
        const float pa3 = fsigmoid(ra.w) * ANGLE_RANGE - ANGLE_RANGE * 0.5f;
        const float pc3 = fsigmoid(rc.w);
        ws[5] = make_float4(pw3, ph3, pa3, pc3);
    }

    __syncwarp();

    // drain: warp's output region is 3072B contiguous -> 6 coalesced STG.128
    const float4* wr = (const float4*)(stage + warp * (PIX_PER_WARP * 6));
    float4* og = (float4*)(out + ((size_t)slice * HW + warp_hw) * 6);
#pragma unroll
    for (int r = 0; r < 6; r++)
        og[lane + 32 * r] = wr[lane + 32 * r];
}

extern "C" void kernel_launch(void* const* d_in, const int* in_sizes, int n_in,
                              void* d_out, int out_size)
{
    const float* raw     = (const float*)d_in[0];
    const float* anchors = (const float*)d_in[1];
    const int* img_h_p   = (n_in > 2) ? (const int*)d_in[2] : nullptr;
    const int* img_w_p   = (n_in > 3) ? (const int*)d_in[3] : nullptr;
    float* out = (float*)d_out;

    const int grid = nB * nA * BLOCKS_PER_SLICE;   // 3072 blocks
    rapid_decode_kernel<<<grid, 256>>>(raw, anchors, img_h_p, img_w_p, out);
}